// round 1
// baseline (speedup 1.0000x reference)
#include <cuda_runtime.h>
#include <math.h>

// Problem constants (static shapes from the reference)
#define BB 32
#define TT 512
#define DD 512
#define TS 2304   // target_length - 1

// Scratch (no runtime allocation allowed)
__device__ float g_sig[BB*TT];
__device__ float g_center[BB*TT];
__device__ int   g_shift[BB*TT];
__device__ int   g_len[BB*TT];
__device__ float g_scale[BB*TS];

// ---------------------------------------------------------------------------
// Kernel 1: per-(b,i) prep — cumsum(ds), shifted, center, sig = softplus(sigma)
// One block per batch row, 512 threads, Hillis-Steele inclusive scan.
// ---------------------------------------------------------------------------
__global__ void lr_prep_kernel(const int* __restrict__ ds,
                               const float* __restrict__ sigma) {
    __shared__ int s[TT];
    int b = blockIdx.x;
    int t = threadIdx.x;
    int d = ds[b*TT + t];
    s[t] = d;
    __syncthreads();
    for (int off = 1; off < TT; off <<= 1) {
        int v = (t >= off) ? s[t - off] : 0;
        __syncthreads();
        s[t] += v;
        __syncthreads();
    }
    int len = s[t];
    int sh  = len - d;
    int idx = b*TT + t;
    g_len[idx]    = len;
    g_shift[idx]  = sh;
    g_center[idx] = 0.5f * (float)d + (float)sh;
    float x = sigma[idx];
    // stable softplus: log(1+exp(x))
    float sp = (x > 20.f) ? x : log1pf(expf(x));
    g_sig[idx] = sp;
}

// ---------------------------------------------------------------------------
// Kernel 2: per-(b,t) scale = row_mass / max(den, 1e-12)
// One warp per (b,t) row; reduce 512 phonemes.
// ---------------------------------------------------------------------------
__global__ void lr_scale_kernel() {
    int warp = (blockIdx.x * blockDim.x + threadIdx.x) >> 5;
    int lane = threadIdx.x & 31;
    if (warp >= BB * TS) return;
    int b = warp / TS;
    int t = warp % TS;
    float tr = (float)(t + 1);
    const float* sg  = g_sig    + b*TT;
    const float* ce  = g_center + b*TT;
    const int*   shp = g_shift  + b*TT;
    const int*   lnp = g_len    + b*TT;

    float den = 0.f;
    int   mass = 0;
    #pragma unroll 4
    for (int i = lane; i < TT; i += 32) {
        float s  = sg[i];
        float dl = tr - ce[i];
        den += expf(-0.5f * dl * dl * s * s) * s;
        mass += (t >= shp[i] && t < lnp[i]) ? 1 : 0;
    }
    #pragma unroll
    for (int o = 16; o > 0; o >>= 1) {
        den  += __shfl_down_sync(0xffffffffu, den, o);
        mass += __shfl_down_sync(0xffffffffu, mass, o);
    }
    if (lane == 0)
        g_scale[warp] = (float)mass / fmaxf(den, 1e-12f);
}

// ---------------------------------------------------------------------------
// Kernel 3: fused GEMM. out[b,t,d] = scale[b,t] * sum_i num[b,t,i] * xs[b,i,d]
// Block tile 128(t) x 128(d), 256 threads, 8x8 micro-tile, K-chunk = 16.
// W tile (ash) generated in-SM from sig/center (never hits HBM).
// ---------------------------------------------------------------------------
#define KC 16

__global__ __launch_bounds__(256, 2)
void lr_gemm_kernel(const float* __restrict__ xs, float* __restrict__ out) {
    int b  = blockIdx.z;
    int t0 = blockIdx.y * 128;
    int d0 = blockIdx.x * 128;

    __shared__ float xsh[KC][128];   // xsh[i][d]  (xs chunk)
    __shared__ float ash[KC][128];   // ash[i][t]  (weight chunk)

    int tid = threadIdx.x;
    int tx = tid & 15;     // d-group
    int ty = tid >> 4;     // t-group

    // W-generation mapping: thread handles row ia (i), 8 consecutive t's
    int ia = tid >> 4;           // 0..15 (i within chunk)
    int ta = (tid & 15) * 8;     // 0..120 (t start)

    const float* sgp = g_sig    + b*TT;
    const float* cep = g_center + b*TT;

    float acc[8][8];
    #pragma unroll
    for (int r = 0; r < 8; r++)
        #pragma unroll
        for (int c = 0; c < 8; c++)
            acc[r][c] = 0.f;

    for (int k0 = 0; k0 < TT; k0 += KC) {
        // ---- load xs chunk (16 x 128 floats), fully coalesced float4 ----
        #pragma unroll
        for (int rr = 0; rr < 2; rr++) {
            int v  = tid + 256 * rr;      // 0..511 float4 slots
            int i  = v >> 5;              // 0..15
            int d4 = (v & 31) * 4;        // 0..124
            float4 val = *(const float4*)(xs + ((size_t)(b*TT + k0 + i))*DD + d0 + d4);
            *(float4*)&xsh[i][d4] = val;
        }
        // ---- generate W chunk: num = exp(-0.5*(tr-center)^2*sig^2)*sig ----
        {
            float s    = sgp[k0 + ia];
            float c    = cep[k0 + ia];
            float coef = -0.5f * s * s;
            #pragma unroll
            for (int r = 0; r < 8; r++) {
                float tr = (float)(t0 + ta + r + 1);
                float dl = tr - c;
                ash[ia][ta + r] = expf(coef * dl * dl) * s;
            }
        }
        __syncthreads();

        // ---- 8x8 micro-tile FMA ----
        #pragma unroll
        for (int i = 0; i < KC; i++) {
            float a[8], x[8];
            #pragma unroll
            for (int r = 0; r < 8; r++) a[r] = ash[i][ty + r*16];
            #pragma unroll
            for (int c = 0; c < 8; c++) x[c] = xsh[i][tx + c*16];
            #pragma unroll
            for (int r = 0; r < 8; r++)
                #pragma unroll
                for (int c = 0; c < 8; c++)
                    acc[r][c] += a[r] * x[c];
        }
        __syncthreads();
    }

    // ---- epilogue: apply per-row scale, write out ----
    #pragma unroll
    for (int r = 0; r < 8; r++) {
        int t = t0 + ty + r*16;
        float sc = g_scale[b*TS + t];
        float* op = out + ((size_t)b*TS + t)*DD + d0;
        #pragma unroll
        for (int c = 0; c < 8; c++)
            op[tx + c*16] = acc[r][c] * sc;
    }
}

// ---------------------------------------------------------------------------
// Launcher
// inputs (metadata order): xs f32 [B,T,D], ds i32 [B,T], sigma f32 [B,T],
//                          target_length i32 scalar (static = 2305, unused)
// output: f32 [B, 2304, D]
// ---------------------------------------------------------------------------
extern "C" void kernel_launch(void* const* d_in, const int* in_sizes, int n_in,
                              void* d_out, int out_size) {
    const float* xs    = (const float*)d_in[0];
    const int*   ds    = (const int*)  d_in[1];
    const float* sigma = (const float*)d_in[2];
    float* out = (float*)d_out;

    lr_prep_kernel<<<BB, TT>>>(ds, sigma);

    int nwarps = BB * TS;                 // one warp per (b,t)
    int nblk   = (nwarps * 32 + 255) / 256;
    lr_scale_kernel<<<nblk, 256>>>();

    dim3 grid(DD / 128, TS / 128, BB);    // (4, 18, 32)
    lr_gemm_kernel<<<grid, 256>>>(xs, out);
}

// round 4
// speedup vs baseline: 2.3678x; 2.3678x over previous
#include <cuda_runtime.h>
#include <cstdint>
#include <math.h>

// Static problem shape
#define BB 32
#define TT 512
#define DD 512
#define TS 2304          // target_length - 1

#define BM 128           // t tile
#define BN 128           // d tile
#define BK 16            // k chunk
#define NCHUNK (TT/BK)   // 32

#define ASTR 20          // A smem row stride (words): 8 consecutive rows conflict-free
#define BSTR 136         // B smem row stride (words): 136 % 32 == 8 -> conflict-free

// Device scratch
__device__ float g_sig[BB*TT];
__device__ float g_center[BB*TT];
__device__ int   g_shift[BB*TT];
__device__ int   g_len[BB*TT];
__device__ float g_scale[BB*TS];

__device__ __forceinline__ uint32_t f2tf32(float f) {
    uint32_t u;
    asm("cvt.rna.tf32.f32 %0, %1;" : "=r"(u) : "f"(f));
    return u;
}
__device__ __forceinline__ void mma_tf32(float* c, const uint32_t* a, const uint32_t* b) {
    asm volatile(
        "mma.sync.aligned.m16n8k8.row.col.f32.tf32.tf32.f32 "
        "{%0,%1,%2,%3}, {%4,%5,%6,%7}, {%8,%9}, {%0,%1,%2,%3};"
        : "+f"(c[0]), "+f"(c[1]), "+f"(c[2]), "+f"(c[3])
        : "r"(a[0]), "r"(a[1]), "r"(a[2]), "r"(a[3]), "r"(b[0]), "r"(b[1]));
}

// ---------------------------------------------------------------------------
// Kernel 1: prep — cumsum(ds), center, sig = softplus(sigma)
// ---------------------------------------------------------------------------
__global__ void lr_prep_kernel(const int* __restrict__ ds,
                               const float* __restrict__ sigma) {
    __shared__ int s[TT];
    int b = blockIdx.x, t = threadIdx.x;
    int d = ds[b*TT + t];
    s[t] = d;
    __syncthreads();
    for (int off = 1; off < TT; off <<= 1) {
        int v = (t >= off) ? s[t - off] : 0;
        __syncthreads();
        s[t] += v;
        __syncthreads();
    }
    int len = s[t], sh = len - d, idx = b*TT + t;
    g_len[idx] = len;
    g_shift[idx] = sh;
    g_center[idx] = 0.5f * (float)d + (float)sh;
    float x = sigma[idx];
    g_sig[idx] = (x > 20.f) ? x : log1pf(expf(x));
}

// ---------------------------------------------------------------------------
// Kernel 2: scale[b,t] = row_mass / max(den, 1e-12)   (one warp per (b,t))
// ---------------------------------------------------------------------------
__global__ void lr_scale_kernel() {
    int warp = (blockIdx.x * blockDim.x + threadIdx.x) >> 5;
    int lane = threadIdx.x & 31;
    if (warp >= BB * TS) return;
    int b = warp / TS, t = warp % TS;
    float tr = (float)(t + 1);
    const float* sg = g_sig + b*TT;
    const float* ce = g_center + b*TT;
    const int* shp = g_shift + b*TT;
    const int* lnp = g_len + b*TT;
    float den = 0.f; int mass = 0;
    #pragma unroll 4
    for (int i = lane; i < TT; i += 32) {
        float s = sg[i], dl = tr - ce[i];
        den += __expf(-0.5f * dl * dl * s * s) * s;
        mass += (t >= shp[i] && t < lnp[i]) ? 1 : 0;
    }
    #pragma unroll
    for (int o = 16; o > 0; o >>= 1) {
        den  += __shfl_down_sync(0xffffffffu, den, o);
        mass += __shfl_down_sync(0xffffffffu, mass, o);
    }
    if (lane == 0) g_scale[warp] = (float)mass / fmaxf(den, 1e-12f);
}

// ---------------------------------------------------------------------------
// Kernel 3: fused mma.sync tf32 GEMM
// out[b, t0+m, d0+n] = sum_i (scale*num)[m][i] * xs[b][i][d0+n]
// A (128 x 16/chunk) generated from sig/center (scale folded); B = xs direct.
// ---------------------------------------------------------------------------
__global__ __launch_bounds__(256, 2)
void lr_gemm_mma(const float* __restrict__ xs, float* __restrict__ out) {
    __shared__ uint32_t As[2][BM * ASTR];   // [m][k] tf32 bits
    __shared__ uint32_t Bs[2][BK * BSTR];   // [k][n] tf32 bits

    int tid = threadIdx.x;
    int wid = tid >> 5, lane = tid & 31;
    int g = lane >> 2, tig = lane & 3;
    int wm = wid >> 2;          // 0..1  (64 t-rows each)
    int wn = wid & 3;           // 0..3  (32 d-cols each)

    int b = blockIdx.z, t0 = blockIdx.y * BM, d0 = blockIdx.x * BN;

    // A-generation mapping: 2 threads per row; each does 8 k's
    int ar  = tid >> 1;
    int akh = (tid & 1) * 8;
    float myscale = g_scale[b*TS + t0 + ar];
    float trow = (float)(t0 + ar + 1);
    const float* sgp = g_sig + b*TT;
    const float* cep = g_center + b*TT;
    const float* xp = xs + ((size_t)b*TT) * DD + d0;   // + i*DD + n

    // B-load mapping: 2 float4 per thread per chunk
    int bi0 = tid >> 5;            // rows 0..7
    int bd4 = (tid & 31) * 4;      // cols 0..124

    float c[4][4][4];
    #pragma unroll
    for (int mt = 0; mt < 4; mt++)
        #pragma unroll
        for (int nt = 0; nt < 4; nt++)
            #pragma unroll
            for (int q = 0; q < 4; q++) c[mt][nt][q] = 0.f;

    uint32_t aReg[8];
    uint32_t bReg[2][4];

    auto loadChunk = [&](int k0) {
        #pragma unroll
        for (int r = 0; r < 2; r++) {
            float4 v = *(const float4*)(xp + (size_t)(k0 + bi0 + 8*r) * DD + bd4);
            bReg[r][0] = f2tf32(v.x); bReg[r][1] = f2tf32(v.y);
            bReg[r][2] = f2tf32(v.z); bReg[r][3] = f2tf32(v.w);
        }
        #pragma unroll
        for (int q = 0; q < 8; q++) {
            int i = k0 + akh + q;
            float s = sgp[i], ce = cep[i];
            float dl = trow - ce;
            aReg[q] = f2tf32(__expf(-0.5f * s * s * dl * dl) * s * myscale);
        }
    };
    auto storeChunk = [&](int st) {
        #pragma unroll
        for (int r = 0; r < 2; r++)
            *(uint4*)&Bs[st][(bi0 + 8*r) * BSTR + bd4] = *(uint4*)bReg[r];
        *(uint4*)&As[st][ar * ASTR + akh]     = *(uint4*)&aReg[0];
        *(uint4*)&As[st][ar * ASTR + akh + 4] = *(uint4*)&aReg[4];
    };

    loadChunk(0);
    storeChunk(0);
    __syncthreads();

    for (int k = 0; k < NCHUNK; k++) {
        int st = k & 1;
        if (k < NCHUNK - 1) loadChunk((k + 1) * BK);

        #pragma unroll
        for (int s = 0; s < 2; s++) {
            uint32_t a[4][4], bb[4][2];
            #pragma unroll
            for (int mt = 0; mt < 4; mt++) {
                int base = (wm*64 + mt*16 + g) * ASTR + s*8 + tig;
                a[mt][0] = As[st][base];
                a[mt][1] = As[st][base + 8*ASTR];
                a[mt][2] = As[st][base + 4];
                a[mt][3] = As[st][base + 8*ASTR + 4];
            }
            #pragma unroll
            for (int nt = 0; nt < 4; nt++) {
                int base = (s*8 + tig) * BSTR + wn*32 + nt*8 + g;
                bb[nt][0] = Bs[st][base];
                bb[nt][1] = Bs[st][base + 4*BSTR];
            }
            #pragma unroll
            for (int mt = 0; mt < 4; mt++)
                #pragma unroll
                for (int nt = 0; nt < 4; nt++)
                    mma_tf32(c[mt][nt], a[mt], bb[nt]);
        }

        if (k < NCHUNK - 1) {
            storeChunk(st ^ 1);
            __syncthreads();
        }
    }

    // Epilogue: scale already folded into A; plain stores
    #pragma unroll
    for (int mt = 0; mt < 4; mt++) {
        int r0 = t0 + wm*64 + mt*16 + g;
        float* op0 = out + ((size_t)b*TS + r0) * DD + d0 + wn*32;
        float* op1 = op0 + 8 * DD;   // +8 rows
        #pragma unroll
        for (int nt = 0; nt < 4; nt++) {
            int nn = nt*8 + tig*2;
            *(float2*)(op0 + nn) = make_float2(c[mt][nt][0], c[mt][nt][1]);
            *(float2*)(op1 + nn) = make_float2(c[mt][nt][2], c[mt][nt][3]);
        }
    }
}

// ---------------------------------------------------------------------------
// Launcher. inputs: xs f32 [B,T,D], ds i32 [B,T], sigma f32 [B,T], target i32
// output: f32 [B, 2304, D]
// ---------------------------------------------------------------------------
extern "C" void kernel_launch(void* const* d_in, const int* in_sizes, int n_in,
                              void* d_out, int out_size) {
    const float* xs    = (const float*)d_in[0];
    const int*   ds    = (const int*)  d_in[1];
    const float* sigma = (const float*)d_in[2];
    float* out = (float*)d_out;

    lr_prep_kernel<<<BB, TT>>>(ds, sigma);

    int nwarps = BB * TS;
    int nblk = (nwarps * 32 + 255) / 256;
    lr_scale_kernel<<<nblk, 256>>>();

    dim3 grid(DD / BN, TS / BM, BB);   // (4, 18, 32)
    lr_gemm_mma<<<grid, 256>>>(xs, out);
}

// round 5
// speedup vs baseline: 2.6796x; 1.1317x over previous
#include <cuda_runtime.h>
#include <cstdint>
#include <math.h>

// Static problem shape
#define BB 32
#define TT 512
#define DD 512
#define TS 2304          // target_length - 1

#define BM 128           // t tile
#define BN 128           // d tile
#define BK 16            // k chunk
#define NCHUNK (TT/BK)   // 32

#define ASTR 24          // A smem row stride (words); phase-conflict-free for LDS.64
#define BSTR 136         // B smem row stride (words); 136 % 32 == 8 -> conflict-free

// Device scratch
__device__ float    g_sig[BB*TT];
__device__ float    g_center[BB*TT];
__device__ int      g_shift[BB*TT];
__device__ int      g_len[BB*TT];
__device__ float    g_scale[BB*TS];
__device__ uint32_t g_xsc[(size_t)BB*TT*DD];   // xs pre-converted to tf32 bits (33.5MB)

__device__ __forceinline__ uint32_t f2tf32(float f) {
    uint32_t u;
    asm("cvt.rna.tf32.f32 %0, %1;" : "=r"(u) : "f"(f));
    return u;
}
__device__ __forceinline__ void mma_tf32(float* c, const uint32_t* a, const uint32_t* b) {
    asm volatile(
        "mma.sync.aligned.m16n8k8.row.col.f32.tf32.tf32.f32 "
        "{%0,%1,%2,%3}, {%4,%5,%6,%7}, {%8,%9}, {%0,%1,%2,%3};"
        : "+f"(c[0]), "+f"(c[1]), "+f"(c[2]), "+f"(c[3])
        : "r"(a[0]), "r"(a[1]), "r"(a[2]), "r"(a[3]), "r"(b[0]), "r"(b[1]));
}
__device__ __forceinline__ uint32_t smem_u32(const void* p) {
    uint32_t a;
    asm("{ .reg .u64 t; cvta.to.shared.u64 t, %1; cvt.u32.u64 %0, t; }" : "=r"(a) : "l"(p));
    return a;
}

// ---------------------------------------------------------------------------
// Kernel 1: prep — cumsum(ds), center, sig = softplus(sigma)
// ---------------------------------------------------------------------------
__global__ void lr_prep_kernel(const int* __restrict__ ds,
                               const float* __restrict__ sigma) {
    __shared__ int s[TT];
    int b = blockIdx.x, t = threadIdx.x;
    int d = ds[b*TT + t];
    s[t] = d;
    __syncthreads();
    for (int off = 1; off < TT; off <<= 1) {
        int v = (t >= off) ? s[t - off] : 0;
        __syncthreads();
        s[t] += v;
        __syncthreads();
    }
    int len = s[t], sh = len - d, idx = b*TT + t;
    g_len[idx] = len;
    g_shift[idx] = sh;
    g_center[idx] = 0.5f * (float)d + (float)sh;
    float x = sigma[idx];
    g_sig[idx] = (x > 20.f) ? x : log1pf(expf(x));
}

// ---------------------------------------------------------------------------
// Kernel 2: scale[b,t] = row_mass / max(den, 1e-12)   (one warp per (b,t))
// ---------------------------------------------------------------------------
__global__ void lr_scale_kernel() {
    int warp = (blockIdx.x * blockDim.x + threadIdx.x) >> 5;
    int lane = threadIdx.x & 31;
    if (warp >= BB * TS) return;
    int b = warp / TS, t = warp % TS;
    float tr = (float)(t + 1);
    const float* sg = g_sig + b*TT;
    const float* ce = g_center + b*TT;
    const int* shp = g_shift + b*TT;
    const int* lnp = g_len + b*TT;
    float den = 0.f; int mass = 0;
    #pragma unroll 4
    for (int i = lane; i < TT; i += 32) {
        float s = sg[i], dl = tr - ce[i];
        den += __expf(-0.5f * dl * dl * s * s) * s;
        mass += (t >= shp[i] && t < lnp[i]) ? 1 : 0;
    }
    #pragma unroll
    for (int o = 16; o > 0; o >>= 1) {
        den  += __shfl_down_sync(0xffffffffu, den, o);
        mass += __shfl_down_sync(0xffffffffu, mass, o);
    }
    if (lane == 0) g_scale[warp] = (float)mass / fmaxf(den, 1e-12f);
}

// ---------------------------------------------------------------------------
// Kernel 3: xs -> tf32 bits (RNA), same layout
// ---------------------------------------------------------------------------
__global__ void lr_cvt_kernel(const float* __restrict__ xs) {
    size_t i = ((size_t)blockIdx.x * blockDim.x + threadIdx.x) * 4;
    float4 v = *(const float4*)(xs + i);
    uint4 u;
    u.x = f2tf32(v.x); u.y = f2tf32(v.y); u.z = f2tf32(v.z); u.w = f2tf32(v.w);
    *(uint4*)(g_xsc + i) = u;
}

// ---------------------------------------------------------------------------
// Kernel 4: fused mma.sync tf32 GEMM.  128 threads, warp tile 64x64 (2x2).
// A (128x16/chunk) generated in SMEM with k-pair-interleaved layout so the
// (tig, tig+4) fragment pair is one LDS.64. B: cp.async from g_xsc.
// ---------------------------------------------------------------------------
__global__ __launch_bounds__(128, 2)
void lr_gemm_mma(float* __restrict__ out) {
    __shared__ uint32_t As[2][BM * ASTR];   // 24.6 KB
    __shared__ uint32_t Bs[2][BK * BSTR];   // 17.4 KB
    __shared__ float sSig[TT], sCen[TT];    // 4 KB

    int tid = threadIdx.x;
    int wid = tid >> 5, lane = tid & 31;
    int g = lane >> 2, tig = lane & 3;
    int wm = wid >> 1;          // 0..1 (64 t-rows)
    int wn = wid & 1;           // 0..1 (64 d-cols)

    int b = blockIdx.z, t0 = blockIdx.y * BM, d0 = blockIdx.x * BN;

    for (int i = tid; i < TT; i += 128) {
        sSig[i] = g_sig[b*TT + i];
        sCen[i] = g_center[b*TT + i];
    }

    int row = tid;   // A-generation: one thread per m-row
    float myscale = g_scale[b*TS + t0 + row];
    float trow = (float)(t0 + row + 1);
    const uint32_t* bp = g_xsc + ((size_t)b*TT) * DD + d0;

    // cp.async mapping: 4 x 16B per thread per chunk
    int bw = lane * 4;   // word col within row

    auto cpB = [&](int st, int k0) {
        #pragma unroll
        for (int it = 0; it < 4; it++) {
            int r = (tid >> 5) + 4 * it;
            uint32_t dst = smem_u32(&Bs[st][r * BSTR + bw]);
            const uint32_t* src = bp + (size_t)(k0 + r) * DD + bw;
            asm volatile("cp.async.cg.shared.global [%0], [%1], 16;" :: "r"(dst), "l"(src));
        }
        asm volatile("cp.async.commit_group;" ::: "memory");
    };
    uint32_t aNext[16];
    auto genA = [&](int k0) {
        #pragma unroll
        for (int j = 0; j < 16; j++) {
            // physical slot j holds logical k = s*8 + (jj>>1) + 4*(jj&1)
            int jj = j & 7;
            int k = k0 + (j >> 3) * 8 + (jj >> 1) + 4 * (jj & 1);
            float s = sSig[k], c = sCen[k];
            float dl = trow - c;
            aNext[j] = f2tf32(__expf(-0.5f * s * s * dl * dl) * s * myscale);
        }
    };
    auto stA = [&](int st) {
        uint32_t* p = &As[st][row * ASTR];
        *(uint4*)(p + 0)  = *(uint4*)&aNext[0];
        *(uint4*)(p + 4)  = *(uint4*)&aNext[4];
        *(uint4*)(p + 8)  = *(uint4*)&aNext[8];
        *(uint4*)(p + 12) = *(uint4*)&aNext[12];
    };

    float acc[4][8][4];
    #pragma unroll
    for (int mt = 0; mt < 4; mt++)
        #pragma unroll
        for (int nt = 0; nt < 8; nt++)
            #pragma unroll
            for (int q = 0; q < 4; q++) acc[mt][nt][q] = 0.f;

    // prologue
    cpB(0, 0);
    __syncthreads();          // sSig/sCen ready
    genA(0);
    stA(0);
    asm volatile("cp.async.wait_group 0;" ::: "memory");
    __syncthreads();

    for (int k = 0; k < NCHUNK; k++) {
        int st = k & 1;
        if (k + 1 < NCHUNK) { cpB(st ^ 1, (k + 1) * BK); genA((k + 1) * BK); }

        #pragma unroll
        for (int s = 0; s < 2; s++) {
            uint32_t a[4][4], bb[8][2];
            #pragma unroll
            for (int mt = 0; mt < 4; mt++) {
                int r0 = wm*64 + mt*16 + g;
                uint2 lo = *(const uint2*)&As[st][r0 * ASTR + s*8 + tig*2];
                uint2 hi = *(const uint2*)&As[st][(r0 + 8) * ASTR + s*8 + tig*2];
                a[mt][0] = lo.x; a[mt][2] = lo.y;   // (g, tig), (g, tig+4)
                a[mt][1] = hi.x; a[mt][3] = hi.y;   // (g+8, tig), (g+8, tig+4)
            }
            #pragma unroll
            for (int nt = 0; nt < 8; nt++) {
                int col = wn*64 + nt*8 + g;
                bb[nt][0] = Bs[st][(s*8 + tig) * BSTR + col];
                bb[nt][1] = Bs[st][(s*8 + tig + 4) * BSTR + col];
            }
            #pragma unroll
            for (int mt = 0; mt < 4; mt++)
                #pragma unroll
                for (int nt = 0; nt < 8; nt++)
                    mma_tf32(acc[mt][nt], a[mt], bb[nt]);
        }

        if (k + 1 < NCHUNK) {
            stA(st ^ 1);
            asm volatile("cp.async.wait_group 0;" ::: "memory");
        }
        __syncthreads();
    }

    // Epilogue: scale folded into A; plain stores
    #pragma unroll
    for (int mt = 0; mt < 4; mt++) {
        int r0 = t0 + wm*64 + mt*16 + g;
        float* op0 = out + ((size_t)b*TS + r0) * DD + d0 + wn*64;
        float* op1 = op0 + 8 * DD;
        #pragma unroll
        for (int nt = 0; nt < 8; nt++) {
            int nn = nt*8 + tig*2;
            *(float2*)(op0 + nn) = make_float2(acc[mt][nt][0], acc[mt][nt][1]);
            *(float2*)(op1 + nn) = make_float2(acc[mt][nt][2], acc[mt][nt][3]);
        }
    }
}

// ---------------------------------------------------------------------------
// Launcher. inputs: xs f32 [B,T,D], ds i32 [B,T], sigma f32 [B,T], target i32
// output: f32 [B, 2304, D]
// ---------------------------------------------------------------------------
extern "C" void kernel_launch(void* const* d_in, const int* in_sizes, int n_in,
                              void* d_out, int out_size) {
    const float* xs    = (const float*)d_in[0];
    const int*   ds    = (const int*)  d_in[1];
    const float* sigma = (const float*)d_in[2];
    float* out = (float*)d_out;

    lr_prep_kernel<<<BB, TT>>>(ds, sigma);

    int nwarps = BB * TS;
    int nblk = (nwarps * 32 + 255) / 256;
    lr_scale_kernel<<<nblk, 256>>>();

    size_t nelem = (size_t)BB * TT * DD;
    lr_cvt_kernel<<<(unsigned)(nelem / (256 * 4)), 256>>>(xs);

    dim3 grid(DD / BN, TS / BM, BB);   // (4, 18, 32)
    lr_gemm_mma<<<grid, 128>>>(out);
}

// round 6
// speedup vs baseline: 3.9485x; 1.4736x over previous
#include <cuda_runtime.h>
#include <cuda_fp16.h>
#include <cstdint>
#include <math.h>

// Static problem shape
#define BB 32
#define TT 512
#define DD 512
#define TS 2304          // target_length - 1

#define BM 128           // t tile
#define BN 256           // d tile
#define BK 16            // k chunk
#define NCHUNK (TT/BK)   // 32

#define ASTR 8           // A smem row stride (words, 16 halves, no pad: conflict-free)
#define BSTR 264         // B smem row stride (words); 264 % 32 == 8 -> conflict-free

// Device scratch
__device__ float    g_sig[BB*TT];
__device__ float    g_center[BB*TT];
__device__ int      g_shift[BB*TT];
__device__ int      g_len[BB*TT];
__device__ float    g_scale[BB*TS];
// xs packed fp16, k-pair-major: word(b, ip, d) = half2(xs[b][2ip][d], xs[b][2ip+1][d])
__device__ uint32_t g_xsh[(size_t)BB*(TT/2)*DD];   // 16.8 MB

__device__ __forceinline__ void mma_fp16(float* c, const uint32_t* a, const uint32_t* b) {
    asm volatile(
        "mma.sync.aligned.m16n8k16.row.col.f32.f16.f16.f32 "
        "{%0,%1,%2,%3}, {%4,%5,%6,%7}, {%8,%9}, {%0,%1,%2,%3};"
        : "+f"(c[0]), "+f"(c[1]), "+f"(c[2]), "+f"(c[3])
        : "r"(a[0]), "r"(a[1]), "r"(a[2]), "r"(a[3]), "r"(b[0]), "r"(b[1]));
}
__device__ __forceinline__ uint32_t smem_u32(const void* p) {
    uint32_t a;
    asm("{ .reg .u64 t; cvta.to.shared.u64 t, %1; cvt.u32.u64 %0, t; }" : "=r"(a) : "l"(p));
    return a;
}
__device__ __forceinline__ uint32_t pack_h2(float lo, float hi) {
    __half2 h = __floats2half2_rn(lo, hi);
    return *(uint32_t*)&h;
}

// ---------------------------------------------------------------------------
// Kernel 1: prep — cumsum(ds), center, sig = softplus(sigma)
// ---------------------------------------------------------------------------
__global__ void lr_prep_kernel(const int* __restrict__ ds,
                               const float* __restrict__ sigma) {
    __shared__ int s[TT];
    int b = blockIdx.x, t = threadIdx.x;
    int d = ds[b*TT + t];
    s[t] = d;
    __syncthreads();
    for (int off = 1; off < TT; off <<= 1) {
        int v = (t >= off) ? s[t - off] : 0;
        __syncthreads();
        s[t] += v;
        __syncthreads();
    }
    int len = s[t], sh = len - d, idx = b*TT + t;
    g_len[idx] = len;
    g_shift[idx] = sh;
    g_center[idx] = 0.5f * (float)d + (float)sh;
    float x = sigma[idx];
    g_sig[idx] = (x > 20.f) ? x : log1pf(expf(x));
}

// ---------------------------------------------------------------------------
// Kernel 2: scale[b,t] = row_mass / max(den, 1e-12)   (one warp per (b,t))
// ---------------------------------------------------------------------------
__global__ void lr_scale_kernel() {
    int warp = (blockIdx.x * blockDim.x + threadIdx.x) >> 5;
    int lane = threadIdx.x & 31;
    if (warp >= BB * TS) return;
    int b = warp / TS, t = warp % TS;
    float tr = (float)(t + 1);
    const float* sg = g_sig + b*TT;
    const float* ce = g_center + b*TT;
    const int* shp = g_shift + b*TT;
    const int* lnp = g_len + b*TT;
    float den = 0.f; int mass = 0;
    #pragma unroll 4
    for (int i = lane; i < TT; i += 32) {
        float s = sg[i], dl = tr - ce[i];
        den += __expf(-0.5f * dl * dl * s * s) * s;
        mass += (t >= shp[i] && t < lnp[i]) ? 1 : 0;
    }
    #pragma unroll
    for (int o = 16; o > 0; o >>= 1) {
        den  += __shfl_down_sync(0xffffffffu, den, o);
        mass += __shfl_down_sync(0xffffffffu, mass, o);
    }
    if (lane == 0) g_scale[warp] = (float)mass / fmaxf(den, 1e-12f);
}

// ---------------------------------------------------------------------------
// Kernel 3: xs -> fp16 k-pair-packed words
// ---------------------------------------------------------------------------
__global__ void lr_cvt_kernel(const float* __restrict__ xs) {
    size_t w4 = ((size_t)blockIdx.x * blockDim.x + threadIdx.x) * 4;  // word base
    size_t row = w4 / DD;            // b*(TT/2) + ip
    int d = (int)(w4 % DD);
    size_t b = row / (TT/2);
    size_t ip = row % (TT/2);
    const float* r0 = xs + (b*TT + 2*ip) * DD + d;
    float4 v0 = *(const float4*)r0;
    float4 v1 = *(const float4*)(r0 + DD);
    uint4 u;
    u.x = pack_h2(v0.x, v1.x);
    u.y = pack_h2(v0.y, v1.y);
    u.z = pack_h2(v0.z, v1.z);
    u.w = pack_h2(v0.w, v1.w);
    *(uint4*)(g_xsh + w4) = u;
}

// ---------------------------------------------------------------------------
// Kernel 4: fused fp16 m16n8k16 GEMM. 256 threads, CTA 128x256, warp 64x64.
// A (W tile, scale folded) generated per chunk into SMEM as packed half2
// words with (w, w+4) logical-word interleave -> fragment pair is one LDS.64.
// B: cp.async from g_xsh (already k-pair packed).
// ---------------------------------------------------------------------------
__global__ __launch_bounds__(256, 1)
void lr_gemm_mma(float* __restrict__ out) {
    __shared__ uint32_t As[2][BM * ASTR];   // 8 KB
    __shared__ uint32_t Bs[2][(BK/2) * BSTR];  // 16.5 KB
    __shared__ float sSig[TT], sCen[TT];    // 4 KB

    int tid = threadIdx.x;
    int wid = tid >> 5, lane = tid & 31;
    int g = lane >> 2, tig = lane & 3;
    int wm = wid >> 2;          // 0..1 (64 t-rows)
    int wn = wid & 3;           // 0..3 (64 d-cols)

    int b = blockIdx.z, t0 = blockIdx.y * BM, d0 = blockIdx.x * BN;

    const uint32_t* bp = g_xsh + ((size_t)b * (TT/2)) * DD + d0;

    // cp.async B: 8 kp-rows x 256 words per chunk; 2 x 16B per thread
    auto cpB = [&](int st, int k0) {
        #pragma unroll
        for (int it = 0; it < 2; it++) {
            int slot = tid + 256 * it;     // 0..511
            int r  = slot >> 6;            // 0..7
            int w4 = (slot & 63) * 4;      // 0..252
            uint32_t dst = smem_u32(&Bs[st][r * BSTR + w4]);
            const uint32_t* src = bp + (size_t)(k0/2 + r) * DD + w4;
            asm volatile("cp.async.cg.shared.global [%0], [%1], 16;" :: "r"(dst), "l"(src));
        }
        asm volatile("cp.async.commit_group;" ::: "memory");
    };

    // A generation: 2 threads per row; each makes 4 packed words (8 exps)
    int arow = tid >> 1;
    float myscale = g_scale[b*TS + t0 + arow];
    float trow = (float)(t0 + arow + 1);
    uint32_t aNext[4];
    auto genA = [&](int k0) {
        #pragma unroll
        for (int j = 0; j < 4; j++) {
            int p  = ((tid & 1) << 2) + j;                  // physical word 0..7
            int lw = (p & 1) ? (p >> 1) + 4 : (p >> 1);     // logical word
            int k  = k0 + 2*lw;
            float s0 = sSig[k],   c0 = sCen[k];
            float s1 = sSig[k+1], c1 = sCen[k+1];
            float dl0 = trow - c0, dl1 = trow - c1;
            float e0 = __expf(-0.5f * s0 * s0 * dl0 * dl0) * s0 * myscale;
            float e1 = __expf(-0.5f * s1 * s1 * dl1 * dl1) * s1 * myscale;
            aNext[j] = pack_h2(e0, e1);
        }
    };
    auto stA = [&](int st) {
        *(uint4*)&As[st][arow * ASTR + (tid & 1) * 4] = *(uint4*)aNext;
    };

    float acc[4][8][4];
    #pragma unroll
    for (int mt = 0; mt < 4; mt++)
        #pragma unroll
        for (int nt = 0; nt < 8; nt++)
            #pragma unroll
            for (int q = 0; q < 4; q++) acc[mt][nt][q] = 0.f;

    // prologue
    cpB(0, 0);
    for (int i = tid; i < TT; i += 256) {
        sSig[i] = g_sig[b*TT + i];
        sCen[i] = g_center[b*TT + i];
    }
    __syncthreads();          // sSig/sCen visible
    genA(0);
    stA(0);
    asm volatile("cp.async.wait_group 0;" ::: "memory");
    __syncthreads();

    for (int k = 0; k < NCHUNK; k++) {
        int st = k & 1;
        if (k + 1 < NCHUNK) { cpB(st ^ 1, (k + 1) * BK); genA((k + 1) * BK); }

        uint32_t a[4][4], bb[8][2];
        #pragma unroll
        for (int mt = 0; mt < 4; mt++) {
            int r0 = wm*64 + mt*16 + g;
            uint2 lo = *(const uint2*)&As[st][r0 * ASTR + tig*2];
            uint2 hi = *(const uint2*)&As[st][(r0 + 8) * ASTR + tig*2];
            a[mt][0] = lo.x; a[mt][1] = hi.x;   // logical word tig (k=2tig..)
            a[mt][2] = lo.y; a[mt][3] = hi.y;   // logical word tig+4 (k=2tig+8..)
        }
        #pragma unroll
        for (int nt = 0; nt < 8; nt++) {
            int col = wn*64 + nt*8 + g;
            bb[nt][0] = Bs[st][tig * BSTR + col];         // kp = tig
            bb[nt][1] = Bs[st][(tig + 4) * BSTR + col];   // kp = tig+4
        }
        #pragma unroll
        for (int mt = 0; mt < 4; mt++)
            #pragma unroll
            for (int nt = 0; nt < 8; nt++)
                mma_fp16(acc[mt][nt], a[mt], bb[nt]);

        if (k + 1 < NCHUNK) {
            stA(st ^ 1);
            asm volatile("cp.async.wait_group 0;" ::: "memory");
        }
        __syncthreads();
    }

    // Epilogue: scale already folded into A; plain stores
    #pragma unroll
    for (int mt = 0; mt < 4; mt++) {
        int r0 = t0 + wm*64 + mt*16 + g;
        float* op0 = out + ((size_t)b*TS + r0) * DD + d0 + wn*64;
        float* op1 = op0 + 8 * DD;
        #pragma unroll
        for (int nt = 0; nt < 8; nt++) {
            int nn = nt*8 + tig*2;
            *(float2*)(op0 + nn) = make_float2(acc[mt][nt][0], acc[mt][nt][1]);
            *(float2*)(op1 + nn) = make_float2(acc[mt][nt][2], acc[mt][nt][3]);
        }
    }
}

// ---------------------------------------------------------------------------
// Launcher. inputs: xs f32 [B,T,D], ds i32 [B,T], sigma f32 [B,T], target i32
// output: f32 [B, 2304, D]
// ---------------------------------------------------------------------------
extern "C" void kernel_launch(void* const* d_in, const int* in_sizes, int n_in,
                              void* d_out, int out_size) {
    const float* xs    = (const float*)d_in[0];
    const int*   ds    = (const int*)  d_in[1];
    const float* sigma = (const float*)d_in[2];
    float* out = (float*)d_out;

    lr_prep_kernel<<<BB, TT>>>(ds, sigma);

    int nwarps = BB * TS;
    int nblk = (nwarps * 32 + 255) / 256;
    lr_scale_kernel<<<nblk, 256>>>();

    size_t nwords = (size_t)BB * (TT/2) * DD;
    lr_cvt_kernel<<<(unsigned)(nwords / (256 * 4)), 256>>>(xs);

    dim3 grid(DD / BN, TS / BM, BB);   // (2, 18, 32)
    lr_gemm_mma<<<grid, 256>>>(out);
}